// round 2
// baseline (speedup 1.0000x reference)
#include <cuda_runtime.h>

// Problem constants
#define NN 32
#define CC 64
#define TTT 256
#define VV 25
#define RR 8
#define OO 64
#define SS 3
#define STREAM_ELEMS (NN*OO*TTT*VV)   // 13,107,200
#define NTV (NN*TTT*VV)               // 204,800 (batchnorm reduction size)

// ---------------- scratch (module globals; no runtime allocation) ------------
__device__ float g_xm[2][NN][CC][VV];              // per-stream mean over T
__device__ float g_r[2][SS][NN][RR][VV];           // r1 / r2
__device__ float g_a[2][SS][NN][OO][VV*VV];        // a1 / a2   (~30.7 MB)
__device__ float g_sum[2][OO];
__device__ float g_sumsq[2][OO];
__device__ float g_mean[2][OO];
__device__ float g_rstd[2][OO];

// ---------------- K0: zero channel stats -------------------------------------
__global__ void k_zero() {
    int i = threadIdx.x;
    if (i < 2*OO) {
        ((float*)g_sum)[i]   = 0.f;
        ((float*)g_sumsq)[i] = 0.f;
    }
}

// ---------------- K1: xm[s][n][c][v] = mean_t x[n,c,t,v] ---------------------
// grid = 2*NN*CC blocks, block = 800 threads (tid enumerates t*25+v for 32 t's)
__global__ void k_mean(const float* __restrict__ x1, const float* __restrict__ x2) {
    int b   = blockIdx.x;
    int s   = b / (NN*CC);
    int rem = b % (NN*CC);
    const float* x = s ? x2 : x1;
    const float* p = x + (size_t)rem * TTT * VV;   // x[n][c][0][0], 6400 contiguous
    int tid = threadIdx.x;                          // 0..799
    float acc = 0.f;
    #pragma unroll
    for (int k = 0; k < 8; k++) acc += p[tid + k*800];
    __shared__ float part[800];
    part[tid] = acc;
    __syncthreads();
    if (tid < VV) {
        float sum = 0.f;
        #pragma unroll
        for (int tg = 0; tg < 32; tg++) sum += part[tg*VV + tid];
        g_xm[s][rem/CC][rem%CC][tid] = sum * (1.0f/TTT);
    }
}

// ---------------- K2: r[s][i][n][r][v] = c_w[i,r,:]·xm[s][n][:,v] + b --------
// grid = SS*NN, block = 512 (400 active: s,r,v)
__global__ void k_r(const float* __restrict__ c1w, const float* __restrict__ c1b,
                    const float* __restrict__ c2w, const float* __restrict__ c2b) {
    int i = blockIdx.x / NN, n = blockIdx.x % NN;
    int tid = threadIdx.x;
    if (tid >= 2*RR*VV) return;
    int s  = tid / (RR*VV);
    int rv = tid % (RR*VV);
    int r  = rv / VV, v = rv % VV;
    const float* w  = s ? c2w : c1w;
    const float* bb = s ? c2b : c1b;
    const float* wrow = w + (i*RR + r)*CC;
    const float* xm   = &g_xm[s][n][0][v];
    float acc = bb[i*RR + r];
    #pragma unroll 8
    for (int c = 0; c < CC; c++) acc += wrow[c] * xm[c*VV];
    g_r[s][i][n][r][v] = acc;
}

// ---------------- K3: rel = tanh(r1[u]-r2[v]); a1,a2 = W·rel + bias + PA/alpha
// grid = SS*NN, block = 256
__global__ void k_a(const float* __restrict__ PA, const float* __restrict__ alpha,
                    const float* __restrict__ c5w, const float* __restrict__ c5b,
                    const float* __restrict__ c6w, const float* __restrict__ c6b) {
    int i = blockIdx.x / NN, n = blockIdx.x % NN;
    __shared__ float rel[RR][VV*VV];
    __shared__ float r1s[RR][VV], r2s[RR][VV];
    int tid = threadIdx.x;
    if (tid < RR*VV) {
        int r = tid/VV, v = tid%VV;
        r1s[r][v] = g_r[0][i][n][r][v];
        r2s[r][v] = g_r[1][i][n][r][v];
    }
    __syncthreads();
    for (int q = tid; q < RR*VV*VV; q += 256) {
        int r = q / (VV*VV), uv = q % (VV*VV);
        int u = uv / VV, v = uv % VV;
        rel[r][uv] = tanhf(r1s[r][u] - r2s[r][v]);
    }
    __syncthreads();
    float al = alpha[0];
    for (int q = tid; q < OO*VV*VV; q += 256) {
        int o = q / (VV*VV), uv = q % (VV*VV);
        float a1 = c5b[i*OO + o] + PA[i*VV*VV + uv];
        float a2 = c6b[i*OO + o] + al;
        #pragma unroll
        for (int r = 0; r < RR; r++) {
            float rv = rel[r][uv];
            a1 += c5w[(i*OO + o)*RR + r] * rv;
            a2 += c6w[(i*OO + o)*RR + r] * rv;
        }
        g_a[0][i][n][o][uv] = a1;
        g_a[1][i][n][o][uv] = a2;
    }
}

// ---------------- K4: fused conv1x1 + graph contraction, y accumulation ------
// block handles (stream s, batch n, 8-channel group o0, 32-row t-tile)
// grid = (T/32=8, O/8=8, 2*N=64), block = 256
__global__ void __launch_bounds__(256, 2)
k_main(const float* __restrict__ x1, const float* __restrict__ x2,
       const float* __restrict__ c3w, const float* __restrict__ c3b,
       const float* __restrict__ c4w, const float* __restrict__ c4b,
       float* __restrict__ out) {
    int tt0 = blockIdx.x * 32;
    int o0  = blockIdx.y * 8;
    int z   = blockIdx.z;
    int s   = z >> 5;
    int n   = z & 31;
    const float* x  = s ? x2  : x1;
    const float* cw = s ? c4w : c3w;
    const float* cb = s ? c4b : c3b;
    float* yout = out + (size_t)s * STREAM_ELEMS;

    __shared__ float ws[8*64];          // weights [g][c] for current subset
    __shared__ float b3s[8];
    __shared__ float x3s[8][32*25];     // conv tile per channel-in-group
    __shared__ float as_[8][VV*VV];     // a-slice per channel-in-group

    int tid  = threadIdx.x;
    int g    = tid >> 5;                // phase-2: warp -> channel offset
    int lane = tid & 31;                // phase-2: lane -> t within tile

    float yacc[VV];
    #pragma unroll
    for (int u = 0; u < VV; u++) yacc[u] = 0.f;

    for (int i = 0; i < SS; i++) {
        // stage weights + bias + a-slice for this subset
        // (512 weight entries staged by 256 threads -> 2 each; R1 bug was tid<512 guard)
        ws[tid]       = cw[(i*OO + o0)*CC + tid];
        ws[tid + 256] = cw[(i*OO + o0)*CC + tid + 256];
        if (tid < 8)   b3s[tid] = cb[i*OO + o0 + tid];
        const float* asrc = &g_a[s][i][n][o0][0];   // 8*625 contiguous floats
        for (int q = tid; q < 8*VV*VV; q += 256)
            ((float*)as_)[q] = asrc[q];
        __syncthreads();

        // ---- phase 1: x3[g][t][v] = sum_c w[g][c] * x[n][c][tt0+t][v] + b[g]
        float acc[4][8];
        #pragma unroll
        for (int k = 0; k < 4; k++)
            #pragma unroll
            for (int gg = 0; gg < 8; gg++) acc[k][gg] = 0.f;

        const float* xp = x + ((size_t)n*CC) * TTT * VV + (size_t)tt0 * VV;
        #pragma unroll 4
        for (int c = 0; c < CC; c++) {
            const float* xc = xp + (size_t)c * TTT * VV;   // 800 contiguous floats
            float xv[4];
            #pragma unroll
            for (int k = 0; k < 4; k++) {
                int p = tid + k*256;
                xv[k] = (p < 800) ? xc[p] : 0.f;
            }
            float wr[8];
            #pragma unroll
            for (int gg = 0; gg < 8; gg++) wr[gg] = ws[gg*64 + c];
            #pragma unroll
            for (int k = 0; k < 4; k++)
                #pragma unroll
                for (int gg = 0; gg < 8; gg++)
                    acc[k][gg] += wr[gg] * xv[k];
        }
        #pragma unroll
        for (int k = 0; k < 4; k++) {
            int p = tid + k*256;
            if (p < 800) {
                #pragma unroll
                for (int gg = 0; gg < 8; gg++)
                    x3s[gg][p] = acc[k][gg] + b3s[gg];
            }
        }
        __syncthreads();

        // ---- phase 2: y[g][t][u] += sum_v a[g][u][v] * x3[g][t][v]
        float xr[VV];
        #pragma unroll
        for (int v = 0; v < VV; v++) xr[v] = x3s[g][lane*VV + v];
        #pragma unroll
        for (int u = 0; u < VV; u++) {
            float zz = 0.f;
            #pragma unroll
            for (int v = 0; v < VV; v++)
                zz += as_[g][u*VV + v] * xr[v];
            yacc[u] += zz;
        }
        __syncthreads();   // before next subset overwrites smem
    }

    // ---- write raw y and per-channel partial stats
    int o = o0 + g;
    int t = tt0 + lane;
    float* yp = yout + ((size_t)(n*OO + o) * TTT + t) * VV;
    float ls = 0.f, lq = 0.f;
    #pragma unroll
    for (int u = 0; u < VV; u++) {
        float yv = yacc[u];
        yp[u] = yv;
        ls += yv;
        lq += yv*yv;
    }
    #pragma unroll
    for (int off = 16; off; off >>= 1) {
        ls += __shfl_down_sync(0xffffffffu, ls, off);
        lq += __shfl_down_sync(0xffffffffu, lq, off);
    }
    if (lane == 0) {
        atomicAdd(&g_sum[s][o],   ls);
        atomicAdd(&g_sumsq[s][o], lq);
    }
}

// ---------------- K5: finalize channel mean / rstd ---------------------------
__global__ void k_stats() {
    int i = threadIdx.x;
    if (i < 2*OO) {
        int s = i / OO, o = i % OO;
        float m = g_sum[s][o] * (1.0f/NTV);
        float v = g_sumsq[s][o] * (1.0f/NTV) - m*m;
        g_mean[s][o] = m;
        g_rstd[s][o] = rsqrtf(v + 1e-5f);
    }
}

// ---------------- K6: BN + residual + ReLU (in place on d_out) ---------------
__global__ void k_bn(const float* __restrict__ x1, const float* __restrict__ x2,
                     const float* __restrict__ bn1w, const float* __restrict__ bn1b,
                     const float* __restrict__ bn2w, const float* __restrict__ bn2b,
                     float* __restrict__ out) {
    const long total4 = 2L * STREAM_ELEMS / 4;
    long stride = (long)gridDim.x * blockDim.x;
    for (long q = (long)blockIdx.x * blockDim.x + threadIdx.x; q < total4; q += stride) {
        long e   = q * 4;
        int  s   = (int)(e / STREAM_ELEMS);
        long rem = e % STREAM_ELEMS;
        int  o   = (int)((rem / (TTT*VV)) % OO);   // float4 never crosses o (6400 | 4)
        const float* bw = s ? bn2w : bn1w;
        const float* bb = s ? bn2b : bn1b;
        const float* xr = s ? x2   : x1;
        float m  = g_mean[s][o], rs = g_rstd[s][o];
        float sc = rs * bw[o];
        float sh = bb[o] - m * sc;
        float4 yv = ((float4*)out)[q];
        float4 xv = ((const float4*)xr)[rem/4];
        yv.x = fmaxf(fmaf(yv.x, sc, sh) + xv.x, 0.f);
        yv.y = fmaxf(fmaf(yv.y, sc, sh) + xv.y, 0.f);
        yv.z = fmaxf(fmaf(yv.z, sc, sh) + xv.z, 0.f);
        yv.w = fmaxf(fmaf(yv.w, sc, sh) + xv.w, 0.f);
        ((float4*)out)[q] = yv;
    }
}

// ---------------- launcher ---------------------------------------------------
extern "C" void kernel_launch(void* const* d_in, const int* in_sizes, int n_in,
                              void* d_out, int out_size) {
    const float* x1    = (const float*)d_in[0];
    const float* x2    = (const float*)d_in[1];
    const float* PA    = (const float*)d_in[2];
    const float* alpha = (const float*)d_in[3];
    const float* c1w   = (const float*)d_in[4];
    const float* c1b   = (const float*)d_in[5];
    const float* c2w   = (const float*)d_in[6];
    const float* c2b   = (const float*)d_in[7];
    const float* c3w   = (const float*)d_in[8];
    const float* c3b   = (const float*)d_in[9];
    const float* c4w   = (const float*)d_in[10];
    const float* c4b   = (const float*)d_in[11];
    const float* c5w   = (const float*)d_in[12];
    const float* c5b   = (const float*)d_in[13];
    const float* c6w   = (const float*)d_in[14];
    const float* c6b   = (const float*)d_in[15];
    const float* bn1w  = (const float*)d_in[16];
    const float* bn1b  = (const float*)d_in[17];
    const float* bn2w  = (const float*)d_in[18];
    const float* bn2b  = (const float*)d_in[19];
    float* out = (float*)d_out;

    k_zero<<<1, 128>>>();
    k_mean<<<2*NN*CC, 800>>>(x1, x2);
    k_r<<<SS*NN, 512>>>(c1w, c1b, c2w, c2b);
    k_a<<<SS*NN, 256>>>(PA, alpha, c5w, c5b, c6w, c6b);
    k_main<<<dim3(TTT/32, OO/8, 2*NN), 256>>>(x1, x2, c3w, c3b, c4w, c4b, out);
    k_stats<<<1, 128>>>();
    k_bn<<<8192, 256>>>(x1, x2, bn1w, bn1b, bn2w, bn2b, out);
}

// round 3
// speedup vs baseline: 1.2062x; 1.2062x over previous
#include <cuda_runtime.h>

// Problem constants
#define NN 32
#define CC 64
#define TTT 256
#define VV 25
#define RR 8
#define OO 64
#define SS 3
#define STREAM_ELEMS (NN*OO*TTT*VV)   // 13,107,200
#define NTV (NN*TTT*VV)               // 204,800

typedef unsigned long long u64;

__device__ __forceinline__ u64 pack2(float lo, float hi) {
    u64 r; asm("mov.b64 %0,{%1,%2};" : "=l"(r) : "f"(lo), "f"(hi)); return r;
}
__device__ __forceinline__ void unpack2(u64 p, float& lo, float& hi) {
    asm("mov.b64 {%0,%1},%2;" : "=f"(lo), "=f"(hi) : "l"(p));
}
__device__ __forceinline__ void ffma2(u64& d, u64 a, u64 b) {
    asm("fma.rn.f32x2 %0,%1,%2,%0;" : "+l"(d) : "l"(a), "l"(b));
}

// ---------------- scratch ----------------------------------------------------
__device__ float g_xm[2][NN][CC][VV];
__device__ float g_r[2][SS][NN][RR][VV];
__device__ float g_a[2][SS][NN][OO][VV*VV];        // ~30.7 MB
__device__ float g_sum[2][OO];
__device__ float g_sumsq[2][OO];
__device__ float g_mean[2][OO];
__device__ float g_rstd[2][OO];

// ---------------- K0 ---------------------------------------------------------
__global__ void k_zero() {
    int i = threadIdx.x;
    if (i < 2*OO) { ((float*)g_sum)[i] = 0.f; ((float*)g_sumsq)[i] = 0.f; }
}

// ---------------- K1: mean over T -------------------------------------------
__global__ void k_mean(const float* __restrict__ x1, const float* __restrict__ x2) {
    int b   = blockIdx.x;
    int s   = b / (NN*CC);
    int rem = b % (NN*CC);
    const float* x = s ? x2 : x1;
    const float* p = x + (size_t)rem * TTT * VV;
    int tid = threadIdx.x;                          // 0..799
    float acc = 0.f;
    #pragma unroll
    for (int k = 0; k < 8; k++) acc += p[tid + k*800];
    __shared__ float part[800];
    part[tid] = acc;
    __syncthreads();
    if (tid < VV) {
        float sum = 0.f;
        #pragma unroll
        for (int tg = 0; tg < 32; tg++) sum += part[tg*VV + tid];
        g_xm[s][rem/CC][rem%CC][tid] = sum * (1.0f/TTT);
    }
}

// ---------------- K2: r = w·xm + b ------------------------------------------
__global__ void k_r(const float* __restrict__ c1w, const float* __restrict__ c1b,
                    const float* __restrict__ c2w, const float* __restrict__ c2b) {
    int i = blockIdx.x / NN, n = blockIdx.x % NN;
    int tid = threadIdx.x;
    if (tid >= 2*RR*VV) return;
    int s  = tid / (RR*VV);
    int rv = tid % (RR*VV);
    int r  = rv / VV, v = rv % VV;
    const float* w  = s ? c2w : c1w;
    const float* bb = s ? c2b : c1b;
    const float* wrow = w + (i*RR + r)*CC;
    const float* xm   = &g_xm[s][n][0][v];
    float acc = bb[i*RR + r];
    #pragma unroll 8
    for (int c = 0; c < CC; c++) acc += wrow[c] * xm[c*VV];
    g_r[s][i][n][r][v] = acc;
}

// ---------------- K3: rel=tanh(r1-r2); a1,a2 = W·rel + bias + PA/alpha -------
// grid = (4 o-quarters, SS*NN), block = 256. a1/a2 packed as f32x2.
__global__ void k_a(const float* __restrict__ PA, const float* __restrict__ alpha,
                    const float* __restrict__ c5w, const float* __restrict__ c5b,
                    const float* __restrict__ c6w, const float* __restrict__ c6b) {
    int bx = blockIdx.x;                 // o-quarter: o in [bx*16, bx*16+16)
    int i  = blockIdx.y / NN, n = blockIdx.y % NN;
    __shared__ float rel[RR][VV*VV];
    __shared__ float r1s[RR][VV], r2s[RR][VV];
    __shared__ u64  wp_s[16*RR];         // (c5w, c6w) pairs for the 16 o's
    int tid = threadIdx.x;
    if (tid < RR*VV) {
        int r = tid/VV, v = tid%VV;
        r1s[r][v] = g_r[0][i][n][r][v];
        r2s[r][v] = g_r[1][i][n][r][v];
    }
    if (tid < 16*RR) {
        int o = tid / RR, r = tid % RR;
        int idx = (i*OO + bx*16 + o)*RR + r;
        wp_s[tid] = pack2(c5w[idx], c6w[idx]);
    }
    __syncthreads();
    for (int q = tid; q < RR*VV*VV; q += 256) {
        int r = q / (VV*VV), uv = q % (VV*VV);
        int u = uv / VV, v = uv % VV;
        rel[r][uv] = tanhf(r1s[r][u] - r2s[r][v]);
    }
    __syncthreads();
    float al = alpha[0];
    for (int q = tid; q < 16*VV*VV; q += 256) {
        int ol = q / (VV*VV), uv = q % (VV*VV);
        int o  = bx*16 + ol;
        float a1 = c5b[i*OO + o] + PA[i*VV*VV + uv];
        float a2 = c6b[i*OO + o] + al;
        u64 acc = pack2(a1, a2);
        #pragma unroll
        for (int r = 0; r < RR; r++) {
            float rv = rel[r][uv];
            ffma2(acc, wp_s[ol*RR + r], pack2(rv, rv));
        }
        float lo, hi; unpack2(acc, lo, hi);
        g_a[0][i][n][o][uv] = lo;
        g_a[1][i][n][o][uv] = hi;
    }
}

// ---------------- K4: fused conv1x1 + graph contraction ----------------------
// grid = (T/32=8, O/8=8, 2*N=64), block = 256. FFMA2 everywhere.
__global__ void __launch_bounds__(256, 2)
k_main(const float* __restrict__ x1, const float* __restrict__ x2,
       const float* __restrict__ c3w, const float* __restrict__ c3b,
       const float* __restrict__ c4w, const float* __restrict__ c4b,
       float* __restrict__ out) {
    int tt0 = blockIdx.x * 32;
    int o0  = blockIdx.y * 8;
    int z   = blockIdx.z;
    int s   = z >> 5;
    int n   = z & 31;
    const float* x  = s ? x2  : x1;
    const float* cw = s ? c4w : c3w;
    const float* cb = s ? c4b : c3b;
    float* yout = out + (size_t)s * STREAM_ELEMS;

    __shared__ __align__(16) float ws_t[CC*8];      // transposed: [c][gg]
    __shared__ __align__(16) float b3s[8];
    __shared__ __align__(16) float x3s[8][32*26];   // conv tile, v-row padded to 26
    __shared__ __align__(16) float as_[8][VV*26];   // a-slice, v-row padded to 26

    int tid  = threadIdx.x;
    int g    = tid >> 5;
    int lane = tid & 31;

    float yacc[VV];
    #pragma unroll
    for (int u = 0; u < VV; u++) yacc[u] = 0.f;

    const float* xbase = x + ((size_t)n*CC)*TTT*VV + (size_t)tt0*VV;

    for (int i = 0; i < SS; i++) {
        // ---- stage weights (transposed), bias, a-slice (padded rows)
        {
            int q = tid;               // 512 = 2*256 weight elems
            int c0 = q >> 3, g0 = q & 7;
            ws_t[q] = cw[(i*OO + o0 + g0)*CC + c0];
            q += 256; c0 = q >> 3; g0 = q & 7;
            ws_t[q] = cw[(i*OO + o0 + g0)*CC + c0];
        }
        if (tid < 8) b3s[tid] = cb[i*OO + o0 + tid];
        {
            const float* asrc = &g_a[s][i][n][o0][0];    // 8*625 contiguous
            for (int q = tid; q < 8*VV*VV; q += 256) {
                int gg  = q / (VV*VV);
                int uv  = q % (VV*VV);
                int u   = uv / VV, v = uv % VV;
                as_[gg][u*26 + v] = asrc[q];
            }
        }
        __syncthreads();

        // ---- phase 1: conv. 200 threads x float4 covers the 800-elem tile.
        if (tid < 200) {
            u64 acc2[4][4];
            #pragma unroll
            for (int e = 0; e < 4; e++)
                #pragma unroll
                for (int gp = 0; gp < 4; gp++) acc2[e][gp] = 0ull;

            #pragma unroll 4
            for (int c = 0; c < CC; c++) {
                float4 xq = *(const float4*)(xbase + (size_t)c*TTT*VV + tid*4);
                u64 xb0 = pack2(xq.x, xq.x);
                u64 xb1 = pack2(xq.y, xq.y);
                u64 xb2 = pack2(xq.z, xq.z);
                u64 xb3 = pack2(xq.w, xq.w);
                const u64* wrow = (const u64*)&ws_t[c*8];
                u64 w0 = wrow[0], w1 = wrow[1], w2 = wrow[2], w3 = wrow[3];
                ffma2(acc2[0][0], xb0, w0); ffma2(acc2[0][1], xb0, w1);
                ffma2(acc2[0][2], xb0, w2); ffma2(acc2[0][3], xb0, w3);
                ffma2(acc2[1][0], xb1, w0); ffma2(acc2[1][1], xb1, w1);
                ffma2(acc2[1][2], xb1, w2); ffma2(acc2[1][3], xb1, w3);
                ffma2(acc2[2][0], xb2, w0); ffma2(acc2[2][1], xb2, w1);
                ffma2(acc2[2][2], xb2, w2); ffma2(acc2[2][3], xb2, w3);
                ffma2(acc2[3][0], xb3, w0); ffma2(acc2[3][1], xb3, w1);
                ffma2(acc2[3][2], xb3, w2); ffma2(acc2[3][3], xb3, w3);
            }
            #pragma unroll
            for (int e = 0; e < 4; e++) {
                int p = tid*4 + e;           // < 800
                int t = p / 25, v = p % 25;
                int tv = t*26 + v;
                #pragma unroll
                for (int gp = 0; gp < 4; gp++) {
                    float lo, hi; unpack2(acc2[e][gp], lo, hi);
                    x3s[2*gp  ][tv] = lo + b3s[2*gp  ];
                    x3s[2*gp+1][tv] = hi + b3s[2*gp+1];
                }
            }
        }
        __syncthreads();

        // ---- phase 2: y[t][u] += sum_v a[u][v] * x3[t][v]  (v packed in pairs)
        {
            const u64* xrow = (const u64*)&x3s[g][lane*26];
            u64 xp[12];
            #pragma unroll
            for (int j = 0; j < 12; j++) xp[j] = xrow[j];
            float xlast = x3s[g][lane*26 + 24];
            #pragma unroll
            for (int u = 0; u < VV; u++) {
                const u64* arow = (const u64*)&as_[g][u*26];
                u64 accA = 0ull, accB = 0ull;
                #pragma unroll
                for (int j = 0; j < 12; j += 2) {
                    ffma2(accA, arow[j],   xp[j]);
                    ffma2(accB, arow[j+1], xp[j+1]);
                }
                float a0, a1, b0, b1;
                unpack2(accA, a0, a1); unpack2(accB, b0, b1);
                yacc[u] += (a0 + a1) + (b0 + b1) + as_[g][u*26 + 24] * xlast;
            }
        }
        __syncthreads();
    }

    // ---- write raw y + channel stats
    int o = o0 + g;
    int t = tt0 + lane;
    float* yp = yout + ((size_t)(n*OO + o) * TTT + t) * VV;
    float ls = 0.f, lq = 0.f;
    #pragma unroll
    for (int u = 0; u < VV; u++) {
        float yv = yacc[u];
        yp[u] = yv;
        ls += yv;
        lq += yv*yv;
    }
    #pragma unroll
    for (int off = 16; off; off >>= 1) {
        ls += __shfl_down_sync(0xffffffffu, ls, off);
        lq += __shfl_down_sync(0xffffffffu, lq, off);
    }
    if (lane == 0) {
        atomicAdd(&g_sum[s][o],   ls);
        atomicAdd(&g_sumsq[s][o], lq);
    }
}

// ---------------- K5 ---------------------------------------------------------
__global__ void k_stats() {
    int i = threadIdx.x;
    if (i < 2*OO) {
        int s = i / OO, o = i % OO;
        float m = g_sum[s][o] * (1.0f/NTV);
        float v = g_sumsq[s][o] * (1.0f/NTV) - m*m;
        g_mean[s][o] = m;
        g_rstd[s][o] = rsqrtf(v + 1e-5f);
    }
}

// ---------------- K6: BN + residual + ReLU -----------------------------------
__global__ void k_bn(const float* __restrict__ x1, const float* __restrict__ x2,
                     const float* __restrict__ bn1w, const float* __restrict__ bn1b,
                     const float* __restrict__ bn2w, const float* __restrict__ bn2b,
                     float* __restrict__ out) {
    const long total4 = 2L * STREAM_ELEMS / 4;
    long stride = (long)gridDim.x * blockDim.x;
    for (long q = (long)blockIdx.x * blockDim.x + threadIdx.x; q < total4; q += stride) {
        long e   = q * 4;
        int  s   = (int)(e / STREAM_ELEMS);
        long rem = e % STREAM_ELEMS;
        int  o   = (int)((rem / (TTT*VV)) % OO);
        const float* bw = s ? bn2w : bn1w;
        const float* bb = s ? bn2b : bn1b;
        const float* xr = s ? x2   : x1;
        float m  = g_mean[s][o], rs = g_rstd[s][o];
        float sc = rs * bw[o];
        float sh = bb[o] - m * sc;
        float4 yv = ((float4*)out)[q];
        float4 xv = ((const float4*)xr)[rem/4];
        yv.x = fmaxf(fmaf(yv.x, sc, sh) + xv.x, 0.f);
        yv.y = fmaxf(fmaf(yv.y, sc, sh) + xv.y, 0.f);
        yv.z = fmaxf(fmaf(yv.z, sc, sh) + xv.z, 0.f);
        yv.w = fmaxf(fmaf(yv.w, sc, sh) + xv.w, 0.f);
        ((float4*)out)[q] = yv;
    }
}

// ---------------- launcher ---------------------------------------------------
extern "C" void kernel_launch(void* const* d_in, const int* in_sizes, int n_in,
                              void* d_out, int out_size) {
    const float* x1    = (const float*)d_in[0];
    const float* x2    = (const float*)d_in[1];
    const float* PA    = (const float*)d_in[2];
    const float* alpha = (const float*)d_in[3];
    const float* c1w   = (const float*)d_in[4];
    const float* c1b   = (const float*)d_in[5];
    const float* c2w   = (const float*)d_in[6];
    const float* c2b   = (const float*)d_in[7];
    const float* c3w   = (const float*)d_in[8];
    const float* c3b   = (const float*)d_in[9];
    const float* c4w   = (const float*)d_in[10];
    const float* c4b   = (const float*)d_in[11];
    const float* c5w   = (const float*)d_in[12];
    const float* c5b   = (const float*)d_in[13];
    const float* c6w   = (const float*)d_in[14];
    const float* c6b   = (const float*)d_in[15];
    const float* bn1w  = (const float*)d_in[16];
    const float* bn1b  = (const float*)d_in[17];
    const float* bn2w  = (const float*)d_in[18];
    const float* bn2b  = (const float*)d_in[19];
    float* out = (float*)d_out;

    k_zero<<<1, 128>>>();
    k_mean<<<2*NN*CC, 800>>>(x1, x2);
    k_r<<<SS*NN, 512>>>(c1w, c1b, c2w, c2b);
    k_a<<<dim3(4, SS*NN), 256>>>(PA, alpha, c5w, c5b, c6w, c6b);
    k_main<<<dim3(TTT/32, OO/8, 2*NN), 256>>>(x1, x2, c3w, c3b, c4w, c4b, out);
    k_stats<<<1, 128>>>();
    k_bn<<<8192, 256>>>(x1, x2, bn1w, bn1b, bn2w, bn2b, out);
}